// round 14
// baseline (speedup 1.0000x reference)
#include <cuda_runtime.h>
#include <cuda_bf16.h>
#include <cstdint>

// DeltaNet fused recurrent decode step (all buffers float32; bf16 rounding
// emulated to match the reference exactly).
//   s1  = bf16(exp(gate) * state) ; acc = k^T s1 ; delta = beta*(v - acc)
//   s2  = bf16(s1 + k (outer) delta) ; out = bf16(q^T s2)
//
// One CTA (512 threads, 16 warps) per (b,h). Warp g owns dk rows
// {g, g+16, ..., g+112}; each lane covers 4 dv columns (one warp = one full
// 512B state row). State streamed once (float4 __ldcs); decayed bf16 state
// cached in 32KB smem for pass 2. 4 CTAs/SM = 64 warps (100% occupancy).

static __device__ __forceinline__ float bf16r(float x) {
    return __bfloat162float(__float2bfloat16(x));
}

static constexpr int D = 128;

__global__ void __launch_bounds__(512, 4)
deltanet_f32_512(const float* __restrict__ q,
                 const float* __restrict__ k,
                 const float* __restrict__ v,
                 const float* __restrict__ beta,
                 const float* __restrict__ gate,
                 const float* __restrict__ state,
                 float* __restrict__ out)
{
    __shared__ __align__(16) __nv_bfloat16 s1sm[D * D];  // 32 KB decayed state
    __shared__ float ksm[D];
    __shared__ float qsm[D];
    __shared__ __align__(16) float red[16][D];           // 8 KB cross-warp partials

    const int bh  = blockIdx.x;
    const int t   = threadIdx.x;
    const int g   = t >> 5;       // warp 0..15
    const int c   = t & 31;
    const int col = 4 * c;        // 4 dv columns per lane (warp spans full row)

    const float* st = state + (size_t)bh * (D * D);

    if (t < D) {
        ksm[t] = __ldg(k + (size_t)bh * D + t);
        qsm[t] = __ldg(q + (size_t)bh * D + t);
    }
    const float decay = expf(__ldg(gate + bh));
    const float betaf = __ldg(beta + bh);
    __syncthreads();

    // ---- Pass 1: s1 = bf16(decay*S) -> smem; acc = k^T s1 ----
    float acc0 = 0.f, acc1 = 0.f, acc2 = 0.f, acc3 = 0.f;

#pragma unroll
    for (int i = 0; i < 8; ++i) {
        const int dk = g + 16 * i;
        // float4 streaming load: 402MB state touched exactly once
        const float4 f = __ldcs(reinterpret_cast<const float4*>(st + (size_t)dk * D + col));

        // bf16 round-to-nearest-even after decay (reference stores s1 as bf16)
        const __nv_bfloat162 p01 =
            __float22bfloat162_rn(make_float2(f.x * decay, f.y * decay));
        const __nv_bfloat162 p23 =
            __float22bfloat162_rn(make_float2(f.z * decay, f.w * decay));

        uint2 pk;
        pk.x = *reinterpret_cast<const uint32_t*>(&p01);
        pk.y = *reinterpret_cast<const uint32_t*>(&p23);
        *reinterpret_cast<uint2*>(s1sm + dk * D + col) = pk;

        const float kf = ksm[dk];
        acc0 += kf * __low2float(p01);
        acc1 += kf * __high2float(p01);
        acc2 += kf * __low2float(p23);
        acc3 += kf * __high2float(p23);
    }

    *reinterpret_cast<float4*>(&red[g][col]) = make_float4(acc0, acc1, acc2, acc3);
    __syncthreads();

    // delta for this lane's 4 columns (each warp computes the same values for
    // its identical column map — no extra synchronization needed)
    float delta[4];
#pragma unroll
    for (int j = 0; j < 4; ++j) {
        float a = 0.f;
#pragma unroll
        for (int w = 0; w < 16; ++w) a += red[w][col + j];
        const float vf = __ldg(v + (size_t)bh * D + col + j);
        delta[j] = betaf * (vf - a);
    }
    __syncthreads();   // red consumed before pass-2 overwrites it

    // ---- Pass 2: out = q^T bf16(s1 + k*delta), s1 from smem (same rows) ----
    float o0 = 0.f, o1 = 0.f, o2 = 0.f, o3 = 0.f;

#pragma unroll
    for (int i = 0; i < 8; ++i) {
        const int dk = g + 16 * i;
        const uint2 pk = *reinterpret_cast<const uint2*>(s1sm + dk * D + col);
        __nv_bfloat162 p01, p23;
        *reinterpret_cast<uint32_t*>(&p01) = pk.x;
        *reinterpret_cast<uint32_t*>(&p23) = pk.y;

        const float kf = ksm[dk];
        const float qf = qsm[dk];

        o0 += qf * bf16r(__low2float(p01)  + kf * delta[0]);
        o1 += qf * bf16r(__high2float(p01) + kf * delta[1]);
        o2 += qf * bf16r(__low2float(p23)  + kf * delta[2]);
        o3 += qf * bf16r(__high2float(p23) + kf * delta[3]);
    }

    *reinterpret_cast<float4*>(&red[g][col]) = make_float4(o0, o1, o2, o3);
    __syncthreads();

    // warp 0 reduces and writes f32 output (bf16-rounded, matching reference)
    if (g == 0) {
        float s[4];
#pragma unroll
        for (int j = 0; j < 4; ++j) {
            float r = 0.f;
#pragma unroll
            for (int w = 0; w < 16; ++w) r += red[w][col + j];
            s[j] = bf16r(r);
        }
        *reinterpret_cast<float4*>(out + (size_t)bh * D + col) =
            make_float4(s[0], s[1], s[2], s[3]);
    }
}

// ---------------- Generic fallback: runtime DK, DV ----------------
__global__ void __launch_bounds__(128)
deltanet_f32_gen(const float* __restrict__ q,
                 const float* __restrict__ k,
                 const float* __restrict__ v,
                 const float* __restrict__ beta,
                 const float* __restrict__ gate,
                 const float* __restrict__ state,
                 float* __restrict__ out,
                 int DK, int DV)
{
    extern __shared__ float dyn[];   // ks[DK], qs[DK]
    float* ks = dyn;
    float* qs = dyn + DK;

    const int bh = blockIdx.x;
    const int t  = threadIdx.x;

    for (int i = t; i < DK; i += 128) {
        ks[i] = __ldg(k + (size_t)bh * DK + i);
        qs[i] = __ldg(q + (size_t)bh * DK + i);
    }
    __syncthreads();

    const float decay = expf(__ldg(gate + bh));
    const float betaf = __ldg(beta + bh);
    const float* S = state + (size_t)bh * DK * DV;

    for (int j = t; j < DV; j += 128) {
        float acc = 0.0f;
        for (int dk = 0; dk < DK; ++dk)
            acc += ks[dk] * bf16r(__ldg(S + (size_t)dk * DV + j) * decay);

        const float delta = betaf * (__ldg(v + (size_t)bh * DV + j) - acc);

        float o = 0.0f;
        for (int dk = 0; dk < DK; ++dk) {
            const float s1 = bf16r(__ldg(S + (size_t)dk * DV + j) * decay);
            o += qs[dk] * bf16r(s1 + ks[dk] * delta);
        }
        out[(size_t)bh * DV + j] = bf16r(o);
    }
}

extern "C" void kernel_launch(void* const* d_in, const int* in_sizes, int n_in,
                              void* d_out, int out_size)
{
    // Insertion order (q, k, v, beta, gate, state); element counts; all f32.
    const float* q     = (const float*)d_in[0];
    const float* k     = (const float*)d_in[1];
    const float* v     = (const float*)d_in[2];
    const float* beta  = (const float*)d_in[3];
    const float* gate  = (const float*)d_in[4];
    const float* state = (const float*)d_in[5];
    float* out = (float*)d_out;

    const long long BH = in_sizes[3];                 // |beta| = B*H
    const long long DK = (long long)in_sizes[0] / BH; // |q| / BH
    const long long DV = (long long)in_sizes[2] / BH; // |v| / BH

    if (DK == 128 && DV == 128) {
        deltanet_f32_512<<<(unsigned)BH, 512>>>(q, k, v, beta, gate, state, out);
    } else {
        const size_t shmem = (size_t)(2 * DK) * sizeof(float);
        deltanet_f32_gen<<<(unsigned)BH, 128, shmem>>>(
            q, k, v, beta, gate, state, out, (int)DK, (int)DV);
    }
}

// round 15
// speedup vs baseline: 1.2575x; 1.2575x over previous
#include <cuda_runtime.h>
#include <cuda_bf16.h>
#include <cstdint>

// DeltaNet fused recurrent decode step (all buffers float32; bf16 rounding
// emulated to match the reference exactly).
//   s1  = bf16(exp(gate) * state) ; acc = k^T s1 ; delta = beta*(v - acc)
//   s2  = bf16(s1 + k (outer) delta) ; out = bf16(q^T s2)
//
// One CTA (256 threads, 8 warps) per (b,h): warp g owns dk rows
// [16g, 16g+16), lane covers 4 dv columns. Pass 1 loads are batched 4-deep
// into registers (forced MLP) with incrementing pointers. Decayed bf16 state
// cached in 32KB smem for pass 2. 6 CTAs/SM -> 48 warps.

static __device__ __forceinline__ float bf16r(float x) {
    return __bfloat162float(__float2bfloat16(x));
}

static constexpr int D = 128;

__global__ void __launch_bounds__(256)
deltanet_f32_256(const float* __restrict__ q,
                 const float* __restrict__ k,
                 const float* __restrict__ v,
                 const float* __restrict__ beta,
                 const float* __restrict__ gate,
                 const float* __restrict__ state,
                 float* __restrict__ out)
{
    __shared__ __align__(16) __nv_bfloat16 s1sm[D * D];  // 32 KB decayed state
    __shared__ float ksm[D];
    __shared__ float qsm[D];
    __shared__ __align__(16) float red[8][D];            // 4 KB cross-warp partials

    const int bh  = blockIdx.x;
    const int t   = threadIdx.x;
    const int g   = t >> 5;       // warp: dk rows [16g, 16g+16)
    const int c   = t & 31;
    const int col = 4 * c;        // 4 dv columns per lane

    const int dk0 = g * 16;
    const float* st = state + (size_t)bh * (D * D);

    if (t < D) {
        ksm[t] = __ldg(k + (size_t)bh * D + t);
        qsm[t] = __ldg(q + (size_t)bh * D + t);
    }
    const float decay = expf(__ldg(gate + bh));
    const float betaf = __ldg(beta + bh);
    __syncthreads();

    // ---- Pass 1: s1 = bf16(decay*S) -> smem; acc = k^T s1 ----
    // Loads batched 4-deep: 4 independent LDG.128 issued before any use.
    float acc0 = 0.f, acc1 = 0.f, acc2 = 0.f, acc3 = 0.f;

    const float4* p = reinterpret_cast<const float4*>(st + (size_t)dk0 * D) + c;
    __nv_bfloat16* s1p = s1sm + dk0 * D + col;
    const float* kp = ksm + dk0;

#pragma unroll
    for (int b = 0; b < 4; ++b) {
        // 4 independent streaming loads (rows 4b .. 4b+3 of this warp's slice)
        const float4 f0 = __ldcs(p);
        const float4 f1 = __ldcs(p + 32);
        const float4 f2 = __ldcs(p + 64);
        const float4 f3 = __ldcs(p + 96);
        p += 128;

        float4 fr[4] = {f0, f1, f2, f3};
#pragma unroll
        for (int r = 0; r < 4; ++r) {
            const float4 f = fr[r];
            // bf16 round-to-nearest-even after decay (reference stores s1 bf16)
            const __nv_bfloat162 p01 =
                __float22bfloat162_rn(make_float2(f.x * decay, f.y * decay));
            const __nv_bfloat162 p23 =
                __float22bfloat162_rn(make_float2(f.z * decay, f.w * decay));

            uint2 pk;
            pk.x = *reinterpret_cast<const uint32_t*>(&p01);
            pk.y = *reinterpret_cast<const uint32_t*>(&p23);
            *reinterpret_cast<uint2*>(s1p) = pk;
            s1p += D;

            const float kf = kp[4 * b + r];
            acc0 += kf * __low2float(p01);
            acc1 += kf * __high2float(p01);
            acc2 += kf * __low2float(p23);
            acc3 += kf * __high2float(p23);
        }
    }

    *reinterpret_cast<float4*>(&red[g][col]) = make_float4(acc0, acc1, acc2, acc3);
    __syncthreads();

    float delta[4];
#pragma unroll
    for (int j = 0; j < 4; ++j) {
        float a = 0.f;
#pragma unroll
        for (int w = 0; w < 8; ++w) a += red[w][col + j];
        const float vf = __ldg(v + (size_t)bh * D + col + j);
        delta[j] = betaf * (vf - a);
    }
    __syncthreads();   // red consumed before pass-2 overwrites it

    // ---- Pass 2: out = q^T bf16(s1 + k*delta), s1 from smem (same rows) ----
    float o0 = 0.f, o1 = 0.f, o2 = 0.f, o3 = 0.f;

    const __nv_bfloat16* s1r = s1sm + dk0 * D + col;
#pragma unroll 8
    for (int i = 0; i < 16; ++i) {
        const uint2 pk = *reinterpret_cast<const uint2*>(s1r);
        s1r += D;
        __nv_bfloat162 p01, p23;
        *reinterpret_cast<uint32_t*>(&p01) = pk.x;
        *reinterpret_cast<uint32_t*>(&p23) = pk.y;

        const float kf = kp[i];
        const float qf = qsm[dk0 + i];

        o0 += qf * bf16r(__low2float(p01)  + kf * delta[0]);
        o1 += qf * bf16r(__high2float(p01) + kf * delta[1]);
        o2 += qf * bf16r(__low2float(p23)  + kf * delta[2]);
        o3 += qf * bf16r(__high2float(p23) + kf * delta[3]);
    }

    *reinterpret_cast<float4*>(&red[g][col]) = make_float4(o0, o1, o2, o3);
    __syncthreads();

    // warp 0 reduces and writes f32 output (bf16-rounded, matching reference)
    if (g == 0) {
        float s[4];
#pragma unroll
        for (int j = 0; j < 4; ++j) {
            float r = 0.f;
#pragma unroll
            for (int w = 0; w < 8; ++w) r += red[w][col + j];
            s[j] = bf16r(r);
        }
        *reinterpret_cast<float4*>(out + (size_t)bh * D + col) =
            make_float4(s[0], s[1], s[2], s[3]);
    }
}

// ---------------- Generic fallback: runtime DK, DV ----------------
__global__ void __launch_bounds__(128)
deltanet_f32_gen(const float* __restrict__ q,
                 const float* __restrict__ k,
                 const float* __restrict__ v,
                 const float* __restrict__ beta,
                 const float* __restrict__ gate,
                 const float* __restrict__ state,
                 float* __restrict__ out,
                 int DK, int DV)
{
    extern __shared__ float dyn[];   // ks[DK], qs[DK]
    float* ks = dyn;
    float* qs = dyn + DK;

    const int bh = blockIdx.x;
    const int t  = threadIdx.x;

    for (int i = t; i < DK; i += 128) {
        ks[i] = __ldg(k + (size_t)bh * DK + i);
        qs[i] = __ldg(q + (size_t)bh * DK + i);
    }
    __syncthreads();

    const float decay = expf(__ldg(gate + bh));
    const float betaf = __ldg(beta + bh);
    const float* S = state + (size_t)bh * DK * DV;

    for (int j = t; j < DV; j += 128) {
        float acc = 0.0f;
        for (int dk = 0; dk < DK; ++dk)
            acc += ks[dk] * bf16r(__ldg(S + (size_t)dk * DV + j) * decay);

        const float delta = betaf * (__ldg(v + (size_t)bh * DV + j) - acc);

        float o = 0.0f;
        for (int dk = 0; dk < DK; ++dk) {
            const float s1 = bf16r(__ldg(S + (size_t)dk * DV + j) * decay);
            o += qs[dk] * bf16r(s1 + ks[dk] * delta);
        }
        out[(size_t)bh * DV + j] = bf16r(o);
    }
}

extern "C" void kernel_launch(void* const* d_in, const int* in_sizes, int n_in,
                              void* d_out, int out_size)
{
    // Insertion order (q, k, v, beta, gate, state); element counts; all f32.
    const float* q     = (const float*)d_in[0];
    const float* k     = (const float*)d_in[1];
    const float* v     = (const float*)d_in[2];
    const float* beta  = (const float*)d_in[3];
    const float* gate  = (const float*)d_in[4];
    const float* state = (const float*)d_in[5];
    float* out = (float*)d_out;

    const long long BH = in_sizes[3];                 // |beta| = B*H
    const long long DK = (long long)in_sizes[0] / BH; // |q| / BH
    const long long DV = (long long)in_sizes[2] / BH; // |v| / BH

    if (DK == 128 && DV == 128) {
        deltanet_f32_256<<<(unsigned)BH, 256>>>(q, k, v, beta, gate, state, out);
    } else {
        const size_t shmem = (size_t)(2 * DK) * sizeof(float);
        deltanet_f32_gen<<<(unsigned)BH, 128, shmem>>>(
            q, k, v, beta, gate, state, out, (int)DK, (int)DV);
    }
}